// round 2
// baseline (speedup 1.0000x reference)
#include <cuda_runtime.h>
#include <cstdint>

#define BATCH 16
#define MAXGT 64
#define NCLS 80
#define HWTOT 21824
#define NLVL 5
#define NTILES 86          // tiles per image: 64+16+4+1+1
#define UNITS (NTILES * BATCH)   // 1376
#define GRID_MAIN 1184     // 8 blocks/SM * 148 SMs -> single wave

// Output layout (floats), concatenated in reference return order.
#define OFF_CLS_T 0ULL
#define OFF_CLS_M ((size_t)BATCH * HWTOT * NCLS)            // 27,934,720
#define OFF_NP    (OFF_CLS_M + (size_t)BATCH * HWTOT)       // 28,283,904
#define OFF_REG_T (OFF_NP + BATCH)                          // 28,283,920
#define OFF_REG_M (OFF_REG_T + (size_t)BATCH * HWTOT * 4)   // 29,680,656

struct GtEntry {              // 20 words = 80 B
    int   px1, py1, px2, py2; // pos region (feature coords)
    int   ix1, iy1, ix2, iy2; // ignore region
    int   ux1, uy1, ux2, uy2; // union bbox (warp skip test)
    float area;
    float bx1, by1, bx2, by2; // image-coord box
    int   lab;
    int   pad0, pad1;
};

__device__ GtEntry d_gt[BATCH][NLVL][MAXGT];
__device__ int     d_ngt[BATCH][NLVL];

// Shrunken/clipped region bounds exactly like reference _prop_box.
// __f*_rn intrinsics forbid FMA contraction (floor/ceil boundary safety).
static __device__ __forceinline__ void prop_bounds(
    float px1, float py1, float px2, float py2, float w, float h,
    float a, float ff,
    int& ox1, int& oy1, int& ox2, int& oy2)
{
    float n1 = floorf(__fadd_rn(px1, __fmul_rn(a, w)));
    float m1 = floorf(__fadd_rn(py1, __fmul_rn(a, h)));
    float n2 = ceilf (__fsub_rn(px2, __fmul_rn(a, w)));
    float m2 = ceilf (__fsub_rn(py2, __fmul_rn(a, h)));
    n2 = fminf(fmaxf(fmaxf(n2, n1 + 1.0f), 0.0f), ff);
    m2 = fminf(fmaxf(fmaxf(m2, m1 + 1.0f), 0.0f), ff);
    n1 = fminf(fmaxf(n1, 0.0f), ff - 1.0f);
    m1 = fminf(fmaxf(m1, 0.0f), ff - 1.0f);
    ox1 = (int)n1; oy1 = (int)m1; ox2 = (int)n2; oy2 = (int)m2;
}

// ---- Setup: compact GT data per (img,level) into global scratch; zero num_pos.
__global__ void __launch_bounds__(32)
fsaf_setup(const int* __restrict__ g_levels,
           const float* __restrict__ g_boxes,
           float* __restrict__ out)
{
    const int img  = blockIdx.x / NLVL;
    const int lvl  = blockIdx.x % NLVL;
    const int lane = threadIdx.x;

    if (blockIdx.x == 0 && lane < BATCH) out[OFF_NP + lane] = 0.0f;

    const int stride = 8 << lvl;
    const int f      = 128 >> lvl;

    int base = 0;
    #pragma unroll
    for (int half = 0; half < 2; ++half) {
        const int g = half * 32 + lane;
        const float* bp = g_boxes + ((size_t)img * MAXGT + g) * 5;
        float bx1 = bp[0], by1 = bp[1], bx2 = bp[2], by2 = bp[3];
        int   lab = (int)bp[4];
        bool  valid = (g_levels[img * MAXGT + g] == lvl);

        const float inv = 1.0f / (float)stride;   // exact (power of 2)
        float px1 = bx1 * inv, py1 = by1 * inv, px2 = bx2 * inv, py2 = by2 * inv;
        float w = px2 - px1, h = py2 - py1;
        const float ff = (float)f;

        int pp1x, pp1y, pp2x, pp2y;   // POS_SCALE=0.2 -> a=0.4
        int ii1x, ii1y, ii2x, ii2y;   // IGNORE_SCALE=0.5 -> a=0.25
        prop_bounds(px1, py1, px2, py2, w, h, 0.4f,  ff, pp1x, pp1y, pp2x, pp2y);
        prop_bounds(px1, py1, px2, py2, w, h, 0.25f, ff, ii1x, ii1y, ii2x, ii2y);

        unsigned bm = __ballot_sync(0xffffffffu, valid);
        int pos = base + __popc(bm & ((1u << lane) - 1u));
        if (valid) {
            GtEntry e;
            e.px1 = pp1x; e.py1 = pp1y; e.px2 = pp2x; e.py2 = pp2y;
            e.ix1 = ii1x; e.iy1 = ii1y; e.ix2 = ii2x; e.iy2 = ii2y;
            e.ux1 = min(pp1x, ii1x); e.uy1 = min(pp1y, ii1y);
            e.ux2 = max(pp2x, ii2x); e.uy2 = max(pp2y, ii2y);
            e.area = (bx2 - bx1) * (by2 - by1);
            e.bx1 = bx1; e.by1 = by1; e.bx2 = bx2; e.by2 = by2;
            e.lab = lab; e.pad0 = 0; e.pad1 = 0;
            d_gt[img][lvl][pos] = e;
        }
        base += __popc(bm);
    }
    if (lane == 0) d_ngt[img][lvl] = base;
}

// ---- Main: persistent strided over 1376 (img,tile) units.
__global__ void __launch_bounds__(256)
fsaf_main(float* __restrict__ out)
{
    __shared__ GtEntry sh[2][MAXGT];   // double-buffered: no trailing sync

    const int tid  = threadIdx.x;
    const int lane = tid & 31;
    const int wid  = tid >> 5;

    int it = 0;
    for (int u = blockIdx.x; u < UNITS; u += GRID_MAIN, ++it) {
        const int img = u / NTILES;
        const int bx  = u - img * NTILES;

        int lvl, tile;
        if      (bx < 64) { lvl = 0; tile = bx;      }
        else if (bx < 80) { lvl = 1; tile = bx - 64; }
        else if (bx < 84) { lvl = 2; tile = bx - 80; }
        else if (bx == 84){ lvl = 3; tile = 0;       }
        else              { lvl = 4; tile = 0;       }

        const int stride = 8 << lvl;
        const int f      = 128 >> lvl;
        const int lg     = 7 - lvl;
        const int hw     = f * f;
        const int cellOff = (lvl >= 1 ? 16384 : 0) + (lvl >= 2 ? 4096 : 0)
                          + (lvl >= 3 ? 1024  : 0) + (lvl >= 4 ? 256  : 0);

        const int cell    = tile * 256 + tid;
        const bool active = (cell < hw);
        const size_t imgCell = (size_t)img * HWTOT + cellOff + cell;

        // ---- Front-loaded zero fill of cls_t: 20 independent STG.128 per
        // warp, fully coalesced. Issued BEFORE the barrier so L1tex is busy
        // while the GT copy/compute proceeds.
        const int cellW0 = tile * 256 + (wid << 5);
        const bool fillv = (cellW0 < hw);   // hw multiple of 32 -> whole-warp
        if (fillv) {
            float4* basep = reinterpret_cast<float4*>(
                out + OFF_CLS_T + ((size_t)img * HWTOT + cellOff + cellW0) * NCLS);
            const float4 z = make_float4(0.0f, 0.0f, 0.0f, 0.0f);
            #pragma unroll
            for (int i = 0; i < 20; ++i)
                basep[i * 32 + lane] = z;
        }

        // ---- Cooperative copy of compacted GT table into shared.
        GtEntry* s = sh[it & 1];
        const int n = d_ngt[img][lvl];
        {
            const float* src = reinterpret_cast<const float*>(&d_gt[img][lvl][0]);
            float*       dst = reinterpret_cast<float*>(s);
            const int nw = n * 20;
            for (int i = tid; i < nw; i += 256) dst[i] = src[i];
        }
        __syncthreads();   // also orders the zero-fill before the scatter below

        // ---- Per-cell assignment.
        const int y = cell >> lg;
        const int x = cell & (f - 1);

        // Warp-uniform bounding range of this warp's 32 consecutive cells.
        const int ymin = cellW0 >> lg;
        const int ymax = (cellW0 + 31) >> lg;
        int xlo, xhi;
        if (ymin == ymax) { xlo = cellW0 & (f - 1); xhi = xlo + 31; }
        else              { xlo = 0;                xhi = f - 1;    }

        bool  anyp = false, anyi = false;
        float best = 1.0e10f;
        int   bidx = 0;

        for (int g = 0; g < n; ++g) {
            // Warp-uniform skip: does (pos U ign) bbox intersect warp range?
            if (s[g].ux1 <= xhi && s[g].ux2 > xlo &&
                s[g].uy1 <= ymax && s[g].uy2 > ymin) {
                bool inp = (x >= s[g].px1) & (x < s[g].px2) &
                           (y >= s[g].py1) & (y < s[g].py2);
                bool ini = (x >= s[g].ix1) & (x < s[g].ix2) &
                           (y >= s[g].iy1) & (y < s[g].iy2);
                anyi |= ini;
                float a = s[g].area;
                bool take = inp & (a < best);   // strict < keeps first index (argmin tie-break)
                anyp |= inp;
                if (take) { best = a; bidx = g; }
            }
        }

        // num_pos: warp-aggregated exact integer count.
        unsigned pm = __ballot_sync(0xffffffffu, active && anyp);
        if (lane == 0 && pm)
            atomicAdd(out + OFF_NP + img, (float)__popc(pm));

        if (active) {
            out[OFF_CLS_M + imgCell] = (anyp || !anyi) ? 1.0f : 0.0f;
            out[OFF_REG_M + imgCell] = anyp ? 1.0f : 0.0f;

            float4 rv = make_float4(0.0f, 0.0f, 0.0f, 0.0f);
            if (anyp) {
                float sx = ((float)x + 0.5f) * (float)stride;  // exact
                float sy = ((float)y + 0.5f) * (float)stride;
                rv.x = (sx - s[bidx].bx1) * 0.25f;
                rv.y = (sy - s[bidx].by1) * 0.25f;
                rv.z = (s[bidx].bx2 - sx) * 0.25f;
                rv.w = (s[bidx].by2 - sy) * 0.25f;
            }
            reinterpret_cast<float4*>(out + OFF_REG_T)[imgCell] = rv;

            // one-hot scatter (ordered after the zero fill by __syncthreads)
            if (anyp)
                out[OFF_CLS_T + imgCell * NCLS + s[bidx].lab] = 1.0f;
        }
        // no trailing sync: next iteration writes the other shared buffer
    }
}

extern "C" void kernel_launch(void* const* d_in, const int* in_sizes, int n_in,
                              void* d_out, int out_size)
{
    const int*   levels = (const int*)  d_in[0];  // (16,64) int32
    const float* boxes  = (const float*)d_in[1];  // (16,64,5) float32
    float* out = (float*)d_out;

    fsaf_setup<<<BATCH * NLVL, 32>>>(levels, boxes, out);
    fsaf_main<<<GRID_MAIN, 256>>>(out);
}